// round 8
// baseline (speedup 1.0000x reference)
#include <cuda_runtime.h>
#include <cuda_bf16.h>

// Problem constants
#define N_ROWS 16384
#define SPLIT  100
#define IDIM   128
#define NH     4
#define PD     64
#define OUTD   (NH * PD)        // 256
#define MITERS (SPLIT / 4)      // 25 main iters, 4 segments (2KB) each
#define SLOTS  4                // ring slots of 2KB each (8KB/warp)
#define PRE    3                // 2KB-groups in flight (6KB/warp outstanding)
#define NWARP  4                // warps (rows) per block

// wq[h][i] = sum_o W[h,i,o] * q[h,o]  — precomputed by a tiny kernel
__device__ float g_wq[NH * IDIM];

__global__ void wq_kernel(const float* __restrict__ W, const float* __restrict__ q) {
    int idx = threadIdx.x;                     // 512 threads
    if (idx >= NH * IDIM) return;
    int h = idx >> 7, i = idx & 127;
    const float* Wr = W + ((size_t)(h * IDIM + i)) * PD;
    const float* qr = q + h * PD;
    float acc = 0.f;
#pragma unroll
    for (int o = 0; o < PD; o++) acc = fmaf(Wr[o], qr[o], acc);
    g_wq[idx] = acc;
}

__device__ __forceinline__ void cp16(void* smem_dst, const void* gsrc) {
    unsigned saddr = (unsigned)__cvta_generic_to_shared(smem_dst);
    asm volatile("cp.async.cg.shared.global [%0], [%1], 16;\n" :: "r"(saddr), "l"(gsrc));
}
__device__ __forceinline__ void cp_commit() { asm volatile("cp.async.commit_group;\n"); }
__device__ __forceinline__ void cp_wait_pre() { asm volatile("cp.async.wait_group %0;\n" :: "n"(PRE - 1)); }

// issue one 2KB group (4 segments) for iteration `t` into slot t%SLOTS (no commit)
__device__ __forceinline__ void issue_group(float4 (*slotp)[128], const float* xrow,
                                            int t, int lane) {
    const int s = t & (SLOTS - 1);
    const float* src = xrow + t * 512 + lane * 8;
    cp16(&slotp[s][lane * 2],      src);
    cp16(&slotp[s][lane * 2 + 1],  src + 4);
    cp16(&slotp[s][64 + lane * 2],     src + 256);
    cp16(&slotp[s][64 + lane * 2 + 1], src + 260);
}

__global__ void __launch_bounds__(NWARP * 32)
attn_kernel(const float* __restrict__ x, const float* __restrict__ W,
            float* __restrict__ out) {
    // per-warp ring: SLOTS slots of 4 segments (512 floats = 128 float4 = 2KB)
    __shared__ float4 ring[NWARP][SLOTS][128];   // 32 KB

    const int warp = threadIdx.x >> 5;
    const int lane = threadIdx.x & 31;
    const int half = lane >> 4;                 // which segment of each 1KB pair
    const int p16  = lane & 15;                 // owns i in [p16*8, p16*8+8) of its segment
    const int b3   = (lane >> 3) & 1;           // specialization bits within the 16-half
    const int b2   = (lane >> 2) & 1;
    const int row  = blockIdx.x * NWARP + warp; // grid sized exactly: always < N_ROWS
    const float* xrow = x + (size_t)row * (SPLIT * IDIM);
    float4 (*slotp)[128] = ring[warp];

    // wq fragment for this lane's 8 i-values, all 4 heads (registers)
    float4 wq0[NH], wq1[NH];
#pragma unroll
    for (int h = 0; h < NH; h++) {
        const float4* g = (const float4*)(g_wq + h * IDIM + p16 * 8);
        wq0[h] = g[0];
        wq1[h] = g[1];
    }

    // accumulators: unnormalized weighted x (this lane's 8 i's, per head) + denom
    float4 xb0[NH], xb1[NH];
    float dsum[NH];
#pragma unroll
    for (int h = 0; h < NH; h++) {
        xb0[h] = make_float4(0.f, 0.f, 0.f, 0.f);
        xb1[h] = make_float4(0.f, 0.f, 0.f, 0.f);
        dsum[h] = 0.f;
    }

    // prologue: fill PRE pipeline stages
#pragma unroll
    for (int t = 0; t < PRE; t++) { issue_group(slotp, xrow, t, lane); cp_commit(); }

    for (int t = 0; t < MITERS; t++) {
        cp_wait_pre();   // this thread's 2KB for iteration t complete
        // (no __syncwarp: each lane reads back exactly the bytes it cp'd itself —
        //  dst index lane*2 == half*32 + p16*2 within each KB)

        const int slot = t & (SLOTS - 1);

        // sub-iteration 0: first 1KB of the slot
        float4 xv0 = slotp[slot][half * 32 + p16 * 2];
        float4 xv1 = slotp[slot][half * 32 + p16 * 2 + 1];

        // overlap: issue the next 2KB group while computing.
        // IMPORTANT: commit UNCONDITIONALLY — wait_group's guarantee is keyed to
        // commit order, so the tail needs empty groups to slide the window.
        const int nt = t + PRE;
        if (nt < MITERS) issue_group(slotp, xrow, nt, lane);
        cp_commit();

#pragma unroll
        for (int sub = 0; sub < 2; sub++) {
            if (sub == 1) {
                xv0 = slotp[slot][64 + half * 32 + p16 * 2];
                xv1 = slotp[slot][64 + half * 32 + p16 * 2 + 1];
            }
            // partial scores for this lane's segment, all heads
            float p[NH];
#pragma unroll
            for (int h = 0; h < NH; h++) {
                float a;
                a = xv0.x * wq0[h].x;
                a = fmaf(xv0.y, wq0[h].y, a);
                a = fmaf(xv0.z, wq0[h].z, a);
                a = fmaf(xv0.w, wq0[h].w, a);
                a = fmaf(xv1.x, wq1[h].x, a);
                a = fmaf(xv1.y, wq1[h].y, a);
                a = fmaf(xv1.z, wq1[h].z, a);
                a = fmaf(xv1.w, wq1[h].w, a);
                p[h] = a;
            }

            // specialized butterfly reduction over the 16-lane half (5 shfls)
            float s1 = b3 ? p[0] : p[2];
            float r1 = __shfl_xor_sync(0xffffffffu, s1, 8);
            float q0 = (b3 ? p[2] : p[0]) + r1;          // head 2*b3
            float s2 = b3 ? p[1] : p[3];
            float r2 = __shfl_xor_sync(0xffffffffu, s2, 8);
            float q1 = (b3 ? p[3] : p[1]) + r2;          // head 2*b3+1
            float s3 = b2 ? q0 : q1;
            float r3 = __shfl_xor_sync(0xffffffffu, s3, 4);
            float v  = (b2 ? q1 : q0) + r3;              // head 2*b3+b2
            v += __shfl_xor_sync(0xffffffffu, v, 2);
            v += __shfl_xor_sync(0xffffffffu, v, 1);

            // leaky_relu -> exp, ONE per lane (|score| <~ 15 << 88, fp32-safe)
            float e = __expf(fmaxf(v, 0.2f * v));

            // allgather e across the 4 head groups (3 shfls)
            float g1 = __shfl_xor_sync(0xffffffffu, e, 4);
            float ea = b2 ? g1 : e;     // head 2*b3
            float eb = b2 ? e  : g1;    // head 2*b3+1
            float g2 = __shfl_xor_sync(0xffffffffu, ea, 8);
            float g3 = __shfl_xor_sync(0xffffffffu, eb, 8);
            float e0 = b3 ? g2 : ea;
            float e1 = b3 ? g3 : eb;
            float e2 = b3 ? ea : g2;
            float e3 = b3 ? eb : g3;
            float ev[NH] = {e0, e1, e2, e3};

#pragma unroll
            for (int h = 0; h < NH; h++) {
                float eh = ev[h];
                dsum[h] += eh;
                xb0[h].x = fmaf(eh, xv0.x, xb0[h].x);
                xb0[h].y = fmaf(eh, xv0.y, xb0[h].y);
                xb0[h].z = fmaf(eh, xv0.z, xb0[h].z);
                xb0[h].w = fmaf(eh, xv0.w, xb0[h].w);
                xb1[h].x = fmaf(eh, xv1.x, xb1[h].x);
                xb1[h].y = fmaf(eh, xv1.y, xb1[h].y);
                xb1[h].z = fmaf(eh, xv1.z, xb1[h].z);
                xb1[h].w = fmaf(eh, xv1.w, xb1[h].w);
            }
        }
    }

    // combine the two halves (they handled interleaved segments)
#pragma unroll
    for (int h = 0; h < NH; h++) {
        dsum[h] += __shfl_xor_sync(0xffffffffu, dsum[h], 16);
        xb0[h].x += __shfl_xor_sync(0xffffffffu, xb0[h].x, 16);
        xb0[h].y += __shfl_xor_sync(0xffffffffu, xb0[h].y, 16);
        xb0[h].z += __shfl_xor_sync(0xffffffffu, xb0[h].z, 16);
        xb0[h].w += __shfl_xor_sync(0xffffffffu, xb0[h].w, 16);
        xb1[h].x += __shfl_xor_sync(0xffffffffu, xb1[h].x, 16);
        xb1[h].y += __shfl_xor_sync(0xffffffffu, xb1[h].y, 16);
        xb1[h].z += __shfl_xor_sync(0xffffffffu, xb1[h].z, 16);
        xb1[h].w += __shfl_xor_sync(0xffffffffu, xb1[h].w, 16);
    }

    // stage normalized xbar into (now-idle) ring space: 512 floats per warp
    float* sx = (float*)&slotp[0][0];
    __syncwarp();   // all lanes done reading the ring before overwrite
    if (half == 0) {
#pragma unroll
        for (int h = 0; h < NH; h++) {
            float inv = 1.0f / dsum[h];
            float4 v0 = xb0[h], v1 = xb1[h];
            v0.x *= inv; v0.y *= inv; v0.z *= inv; v0.w *= inv;
            v1.x *= inv; v1.y *= inv; v1.z *= inv; v1.w *= inv;
            float4* dst = (float4*)(sx + h * IDIM + p16 * 8);
            dst[0] = v0;
            dst[1] = v1;
        }
    }
    __syncwarp();

    // epilogue GEMV: pooled[h,o] = sum_i xbarN[h,i] * W[h,i,o]
    const int h2 = lane >> 3;
    const int cb = lane & 7;
    const float4* Wv = (const float4*)W + (size_t)h2 * IDIM * (PD / 4) + cb * 2;
    const float* sxh = sx + h2 * IDIM;
    float4 a0 = make_float4(0.f, 0.f, 0.f, 0.f);
    float4 a1 = make_float4(0.f, 0.f, 0.f, 0.f);
#pragma unroll 8
    for (int i = 0; i < IDIM; i++) {
        float xv = sxh[i];                       // broadcast within 8-lane group
        float4 w0 = Wv[i * (PD / 4)];
        float4 w1 = Wv[i * (PD / 4) + 1];
        a0.x = fmaf(xv, w0.x, a0.x);
        a0.y = fmaf(xv, w0.y, a0.y);
        a0.z = fmaf(xv, w0.z, a0.z);
        a0.w = fmaf(xv, w0.w, a0.w);
        a1.x = fmaf(xv, w1.x, a1.x);
        a1.y = fmaf(xv, w1.y, a1.y);
        a1.z = fmaf(xv, w1.z, a1.z);
        a1.w = fmaf(xv, w1.w, a1.w);
    }
    float4* op = (float4*)(out + (size_t)row * OUTD + h2 * PD + cb * 8);
    op[0] = a0;
    op[1] = a1;
}

extern "C" void kernel_launch(void* const* d_in, const int* in_sizes, int n_in,
                              void* d_out, int out_size) {
    // inputs: x [N, 12800], W [4,128,64], q [4,64] — identify defensively by size
    const float* x = (const float*)d_in[0];
    const float* W = (const float*)d_in[1];
    const float* q = (const float*)d_in[2];
    for (int i = 0; i < n_in && i < 3; i++) {
        if (in_sizes[i] == N_ROWS * SPLIT * IDIM) x = (const float*)d_in[i];
        else if (in_sizes[i] == NH * IDIM * PD)   W = (const float*)d_in[i];
        else if (in_sizes[i] == NH * PD)          q = (const float*)d_in[i];
    }
    float* out = (float*)d_out;

    wq_kernel<<<1, 512>>>(W, q);
    attn_kernel<<<N_ROWS / NWARP, NWARP * 32>>>(x, W, out);
}

// round 9
// speedup vs baseline: 1.1618x; 1.1618x over previous
#include <cuda_runtime.h>
#include <cuda_bf16.h>

// Problem constants
#define N_ROWS 16384
#define SPLIT  100
#define IDIM   128
#define NH     4
#define PD     64
#define OUTD   (NH * PD)        // 256
#define MITERS (SPLIT / 4)      // 25 main iters, 4 segments (2KB) each
#define SLOTS  4                // ring slots of 2KB each (8KB/warp)
#define PRE    3                // 2KB-groups in flight (6KB/warp outstanding)
#define NWARP  4                // warps (rows) per block

// wq[h][i] = sum_o W[h,i,o] * q[h,o]  — precomputed by a tiny kernel
__device__ float g_wq[NH * IDIM];

__global__ void wq_kernel(const float* __restrict__ W, const float* __restrict__ q) {
    int idx = threadIdx.x;                     // 512 threads
    if (idx >= NH * IDIM) return;
    int h = idx >> 7, i = idx & 127;
    const float* Wr = W + ((size_t)(h * IDIM + i)) * PD;
    const float* qr = q + h * PD;
    float acc = 0.f;
#pragma unroll
    for (int o = 0; o < PD; o++) acc = fmaf(Wr[o], qr[o], acc);
    g_wq[idx] = acc;
}

__device__ __forceinline__ void cp16(void* smem_dst, const void* gsrc) {
    unsigned saddr = (unsigned)__cvta_generic_to_shared(smem_dst);
    asm volatile("cp.async.cg.shared.global [%0], [%1], 16;\n" :: "r"(saddr), "l"(gsrc));
}
__device__ __forceinline__ void cp_commit() { asm volatile("cp.async.commit_group;\n"); }
__device__ __forceinline__ void cp_wait_pre() { asm volatile("cp.async.wait_group %0;\n" :: "n"(PRE - 1)); }

// issue one 2KB group (4 segments) for iteration `t` into slot t%SLOTS (no commit)
__device__ __forceinline__ void issue_group(float4 (*slotp)[128], const float* xrow,
                                            int t, int lane) {
    const int s = t & (SLOTS - 1);
    const float* src = xrow + t * 512 + lane * 8;
    cp16(&slotp[s][lane * 2],      src);
    cp16(&slotp[s][lane * 2 + 1],  src + 4);
    cp16(&slotp[s][64 + lane * 2],     src + 256);
    cp16(&slotp[s][64 + lane * 2 + 1], src + 260);
}

__global__ void __launch_bounds__(NWARP * 32)
attn_kernel(const float* __restrict__ x, const float* __restrict__ W,
            float* __restrict__ out) {
    // per-warp ring: SLOTS slots of 4 segments (512 floats = 128 float4 = 2KB)
    __shared__ float4 ring[NWARP][SLOTS][128];   // 32 KB
    __shared__ float sdsum[NWARP][NH];           // per-row softmax denominators

    const int warp = threadIdx.x >> 5;
    const int lane = threadIdx.x & 31;
    const int half = lane >> 4;                 // which segment of each 1KB pair
    const int p16  = lane & 15;                 // owns i in [p16*8, p16*8+8) of its segment
    const int b3   = (lane >> 3) & 1;           // specialization bits within the 16-half
    const int b2   = (lane >> 2) & 1;
    const int row  = blockIdx.x * NWARP + warp; // grid sized exactly: always < N_ROWS
    const float* xrow = x + (size_t)row * (SPLIT * IDIM);
    float4 (*slotp)[128] = ring[warp];

    // wq fragment for this lane's 8 i-values, all 4 heads (registers)
    float4 wq0[NH], wq1[NH];
#pragma unroll
    for (int h = 0; h < NH; h++) {
        const float4* g = (const float4*)(g_wq + h * IDIM + p16 * 8);
        wq0[h] = g[0];
        wq1[h] = g[1];
    }

    // accumulators: unnormalized weighted x (this lane's 8 i's, per head) + denom
    float4 xb0[NH], xb1[NH];
    float dsum[NH];
#pragma unroll
    for (int h = 0; h < NH; h++) {
        xb0[h] = make_float4(0.f, 0.f, 0.f, 0.f);
        xb1[h] = make_float4(0.f, 0.f, 0.f, 0.f);
        dsum[h] = 0.f;
    }

    // prologue: fill PRE pipeline stages
#pragma unroll
    for (int t = 0; t < PRE; t++) { issue_group(slotp, xrow, t, lane); cp_commit(); }

    for (int t = 0; t < MITERS; t++) {
        cp_wait_pre();   // this thread's 2KB for iteration t complete
        // (no __syncwarp: each lane reads back exactly the bytes it cp'd itself)

        const int slot = t & (SLOTS - 1);

        // sub-iteration 0: first 1KB of the slot
        float4 xv0 = slotp[slot][half * 32 + p16 * 2];
        float4 xv1 = slotp[slot][half * 32 + p16 * 2 + 1];

        // overlap: issue the next 2KB group while computing.
        // commit UNCONDITIONALLY — wait_group is keyed to commit order, so the
        // tail needs empty groups to slide the window forward.
        const int nt = t + PRE;
        if (nt < MITERS) issue_group(slotp, xrow, nt, lane);
        cp_commit();

#pragma unroll
        for (int sub = 0; sub < 2; sub++) {
            if (sub == 1) {
                xv0 = slotp[slot][64 + half * 32 + p16 * 2];
                xv1 = slotp[slot][64 + half * 32 + p16 * 2 + 1];
            }
            // partial scores for this lane's segment, all heads
            float p[NH];
#pragma unroll
            for (int h = 0; h < NH; h++) {
                float a;
                a = xv0.x * wq0[h].x;
                a = fmaf(xv0.y, wq0[h].y, a);
                a = fmaf(xv0.z, wq0[h].z, a);
                a = fmaf(xv0.w, wq0[h].w, a);
                a = fmaf(xv1.x, wq1[h].x, a);
                a = fmaf(xv1.y, wq1[h].y, a);
                a = fmaf(xv1.z, wq1[h].z, a);
                a = fmaf(xv1.w, wq1[h].w, a);
                p[h] = a;
            }

            // specialized butterfly reduction over the 16-lane half (5 shfls)
            float s1 = b3 ? p[0] : p[2];
            float r1 = __shfl_xor_sync(0xffffffffu, s1, 8);
            float q0 = (b3 ? p[2] : p[0]) + r1;          // head 2*b3
            float s2 = b3 ? p[1] : p[3];
            float r2 = __shfl_xor_sync(0xffffffffu, s2, 8);
            float q1 = (b3 ? p[3] : p[1]) + r2;          // head 2*b3+1
            float s3 = b2 ? q0 : q1;
            float r3 = __shfl_xor_sync(0xffffffffu, s3, 4);
            float v  = (b2 ? q1 : q0) + r3;              // head 2*b3+b2
            v += __shfl_xor_sync(0xffffffffu, v, 2);
            v += __shfl_xor_sync(0xffffffffu, v, 1);

            // leaky_relu -> exp, ONE per lane (|score| <~ 15 << 88, fp32-safe)
            float e = __expf(fmaxf(v, 0.2f * v));

            // allgather e across the 4 head groups (3 shfls)
            float g1 = __shfl_xor_sync(0xffffffffu, e, 4);
            float ea = b2 ? g1 : e;     // head 2*b3
            float eb = b2 ? e  : g1;    // head 2*b3+1
            float g2 = __shfl_xor_sync(0xffffffffu, ea, 8);
            float g3 = __shfl_xor_sync(0xffffffffu, eb, 8);
            float e0 = b3 ? g2 : ea;
            float e1 = b3 ? g3 : eb;
            float e2 = b3 ? ea : g2;
            float e3 = b3 ? eb : g3;
            float ev[NH] = {e0, e1, e2, e3};

#pragma unroll
            for (int h = 0; h < NH; h++) {
                float eh = ev[h];
                dsum[h] += eh;
                xb0[h].x = fmaf(eh, xv0.x, xb0[h].x);
                xb0[h].y = fmaf(eh, xv0.y, xb0[h].y);
                xb0[h].z = fmaf(eh, xv0.z, xb0[h].z);
                xb0[h].w = fmaf(eh, xv0.w, xb0[h].w);
                xb1[h].x = fmaf(eh, xv1.x, xb1[h].x);
                xb1[h].y = fmaf(eh, xv1.y, xb1[h].y);
                xb1[h].z = fmaf(eh, xv1.z, xb1[h].z);
                xb1[h].w = fmaf(eh, xv1.w, xb1[h].w);
            }
        }
    }

    // combine the two halves (they handled interleaved segments)
#pragma unroll
    for (int h = 0; h < NH; h++) {
        dsum[h] += __shfl_xor_sync(0xffffffffu, dsum[h], 16);
        xb0[h].x += __shfl_xor_sync(0xffffffffu, xb0[h].x, 16);
        xb0[h].y += __shfl_xor_sync(0xffffffffu, xb0[h].y, 16);
        xb0[h].z += __shfl_xor_sync(0xffffffffu, xb0[h].z, 16);
        xb0[h].w += __shfl_xor_sync(0xffffffffu, xb0[h].w, 16);
        xb1[h].x += __shfl_xor_sync(0xffffffffu, xb1[h].x, 16);
        xb1[h].y += __shfl_xor_sync(0xffffffffu, xb1[h].y, 16);
        xb1[h].z += __shfl_xor_sync(0xffffffffu, xb1[h].z, 16);
        xb1[h].w += __shfl_xor_sync(0xffffffffu, xb1[h].w, 16);
    }

    // ---- stage UNNORMALIZED xb for ALL rows into block-shared space ----
    // Flat layout over the ring: row r's vector at sx[r*512 + h*128 + i].
    // Row r's region aliases warp 0's ring slots, so ALL warps must be done
    // with the mainloop before anyone writes: full block barrier first.
    float* sx = (float*)&ring[0][0][0];
    __syncthreads();
    if (half == 0) {
#pragma unroll
        for (int h = 0; h < NH; h++) {
            float4* dst = (float4*)(sx + warp * 512 + h * IDIM + p16 * 8);
            dst[0] = xb0[h];
            dst[1] = xb1[h];
        }
    }
    if (lane == 0) {
#pragma unroll
        for (int h = 0; h < NH; h++) sdsum[warp][h] = dsum[h];
    }
    __syncthreads();

    // ---- cooperative epilogue: warp w = head w, lane owns 2 output cols,
    //      each W float2 load amortized across all 4 rows (8 FMAs/load) ----
    {
        const int hh = warp;              // head handled by this warp
        const int c0 = lane * 2;          // output columns c0, c0+1
        const float* Wp = W + ((size_t)hh * IDIM) * PD + c0;  // W[hh][i][c0], stride PD per i
        const float* sxh = sx + hh * IDIM;                    // + r*512 per row

        float2 acc[NWARP];
#pragma unroll
        for (int r = 0; r < NWARP; r++) acc[r] = make_float2(0.f, 0.f);

#pragma unroll 4
        for (int i = 0; i < IDIM; i++) {
            float2 wv = *(const float2*)(Wp + i * PD);         // shared by all 4 rows
#pragma unroll
            for (int r = 0; r < NWARP; r++) {
                float xv = sxh[r * 512 + i];                   // LDS broadcast
                acc[r].x = fmaf(xv, wv.x, acc[r].x);
                acc[r].y = fmaf(xv, wv.y, acc[r].y);
            }
        }

#pragma unroll
        for (int r = 0; r < NWARP; r++) {
            float inv = 1.0f / sdsum[r][hh];
            int row_r = blockIdx.x * NWARP + r;
            float2* op = (float2*)(out + (size_t)row_r * OUTD + hh * PD + c0);
            *op = make_float2(acc[r].x * inv, acc[r].y * inv);
        }
    }
}

extern "C" void kernel_launch(void* const* d_in, const int* in_sizes, int n_in,
                              void* d_out, int out_size) {
    // inputs: x [N, 12800], W [4,128,64], q [4,64] — identify defensively by size
    const float* x = (const float*)d_in[0];
    const float* W = (const float*)d_in[1];
    const float* q = (const float*)d_in[2];
    for (int i = 0; i < n_in && i < 3; i++) {
        if (in_sizes[i] == N_ROWS * SPLIT * IDIM) x = (const float*)d_in[i];
        else if (in_sizes[i] == NH * IDIM * PD)   W = (const float*)d_in[i];
        else if (in_sizes[i] == NH * PD)          q = (const float*)d_in[i];
    }
    float* out = (float*)d_out;

    wq_kernel<<<1, 512>>>(W, q);
    attn_kernel<<<N_ROWS / NWARP, NWARP * 32>>>(x, W, out);
}

// round 11
// speedup vs baseline: 1.2872x; 1.1080x over previous
#include <cuda_runtime.h>
#include <cuda_bf16.h>

// Problem constants
#define N_ROWS 16384
#define SPLIT  100
#define IDIM   128
#define NH     4
#define PD     64
#define OUTD   (NH * PD)        // 256
#define MITERS (SPLIT / 2)      // 50 iters, 1KB (2 segments) each
#define SLOTS  4                // ring slots of 1KB each (4KB/warp)
#define PRE    3                // groups in flight (3KB/warp outstanding)
#define NWARP  4                // warps (rows) per block

// wq[h][i] = sum_o W[h,i,o] * q[h,o]  — precomputed by a tiny kernel
__device__ float g_wq[NH * IDIM];

__global__ void wq_kernel(const float* __restrict__ W, const float* __restrict__ q) {
    int idx = threadIdx.x;                     // 512 threads
    if (idx >= NH * IDIM) return;
    int h = idx >> 7, i = idx & 127;
    const float* Wr = W + ((size_t)(h * IDIM + i)) * PD;
    const float* qr = q + h * PD;
    float acc = 0.f;
#pragma unroll
    for (int o = 0; o < PD; o++) acc = fmaf(Wr[o], qr[o], acc);
    g_wq[idx] = acc;
}

__device__ __forceinline__ void cp16(void* smem_dst, const void* gsrc) {
    unsigned saddr = (unsigned)__cvta_generic_to_shared(smem_dst);
    asm volatile("cp.async.cg.shared.global [%0], [%1], 16;\n" :: "r"(saddr), "l"(gsrc));
}
__device__ __forceinline__ void cp_commit() { asm volatile("cp.async.commit_group;\n"); }
__device__ __forceinline__ void cp_wait_pre() { asm volatile("cp.async.wait_group %0;\n" :: "n"(PRE - 1)); }

__global__ void __launch_bounds__(NWARP * 32, 8)
attn_kernel(const float* __restrict__ x, const float* __restrict__ W,
            float* __restrict__ out) {
    // per-warp ring: SLOTS slots of 2 segments (256 floats = 64 float4 = 1KB)
    __shared__ float4 ring[NWARP][SLOTS][64];    // 16 KB
    __shared__ float sdsum[NWARP][NH];           // per-row softmax denominators

    const int warp = threadIdx.x >> 5;
    const int lane = threadIdx.x & 31;
    const int half = lane >> 4;                 // head-pair owner: heads {2*half, 2*half+1}
    const int p16  = lane & 15;                 // owns i in [p16*8, p16*8+8) of BOTH segments
    const int b3   = (p16 >> 3) & 1;            // head selector within the pair
    const int b2   = (p16 >> 2) & 1;            // segment selector (A/B)
    const int row  = blockIdx.x * NWARP + warp; // grid sized exactly: always < N_ROWS
    const float* xrow = x + (size_t)row * (SPLIT * IDIM);
    float4 (*slotp)[64] = ring[warp];

    // wq fragment: this lane's 8 i-values for its 2 heads (16 regs)
    float4 wqa0, wqa1, wqb0, wqb1;
    {
        const float4* ga = (const float4*)(g_wq + (2 * half) * IDIM + p16 * 8);
        const float4* gb = (const float4*)(g_wq + (2 * half + 1) * IDIM + p16 * 8);
        wqa0 = ga[0]; wqa1 = ga[1];
        wqb0 = gb[0]; wqb1 = gb[1];
    }

    // accumulators: 2 heads x 8 i (16 regs) + 2 denominators
    float4 xh0a, xh0b, xh1a, xh1b;
    xh0a = xh0b = xh1a = xh1b = make_float4(0.f, 0.f, 0.f, 0.f);
    float ds0 = 0.f, ds1 = 0.f;

    // prologue: fill PRE pipeline stages (lane copies float4[lane*2], [lane*2+1])
#pragma unroll
    for (int t = 0; t < PRE; t++) {
        const float* src = xrow + t * 256 + lane * 8;
        cp16(&slotp[t][lane * 2],     src);
        cp16(&slotp[t][lane * 2 + 1], src + 4);
        cp_commit();
    }

    for (int t = 0; t < MITERS; t++) {
        cp_wait_pre();
        __syncwarp();    // lanes read bytes cp'd by OTHER lanes (both halves read both segs)

        const int slot = t & (SLOTS - 1);
        // segment A = float4[0..32), segment B = float4[32..64); lane's i-slice of each
        float4 xa0 = slotp[slot][p16 * 2];
        float4 xa1 = slotp[slot][p16 * 2 + 1];
        float4 xb0v = slotp[slot][32 + p16 * 2];
        float4 xb1v = slotp[slot][32 + p16 * 2 + 1];

        // issue next stage; commit UNCONDITIONALLY (wait_group is commit-order keyed)
        const int nt = t + PRE;
        if (nt < MITERS) {
            const int ns = nt & (SLOTS - 1);
            const float* src = xrow + nt * 256 + lane * 8;
            cp16(&slotp[ns][lane * 2],     src);
            cp16(&slotp[ns][lane * 2 + 1], src + 4);
        }
        cp_commit();

        // partial scores: 2 heads x 2 segments over this lane's 8 i's
        float pA0, pA1, pB0, pB1;
        {
            float a;
            a = xa0.x * wqa0.x;  a = fmaf(xa0.y, wqa0.y, a); a = fmaf(xa0.z, wqa0.z, a); a = fmaf(xa0.w, wqa0.w, a);
            a = fmaf(xa1.x, wqa1.x, a); a = fmaf(xa1.y, wqa1.y, a); a = fmaf(xa1.z, wqa1.z, a); a = fmaf(xa1.w, wqa1.w, a);
            pA0 = a;
            a = xa0.x * wqb0.x;  a = fmaf(xa0.y, wqb0.y, a); a = fmaf(xa0.z, wqb0.z, a); a = fmaf(xa0.w, wqb0.w, a);
            a = fmaf(xa1.x, wqb1.x, a); a = fmaf(xa1.y, wqb1.y, a); a = fmaf(xa1.z, wqb1.z, a); a = fmaf(xa1.w, wqb1.w, a);
            pA1 = a;
            a = xb0v.x * wqa0.x; a = fmaf(xb0v.y, wqa0.y, a); a = fmaf(xb0v.z, wqa0.z, a); a = fmaf(xb0v.w, wqa0.w, a);
            a = fmaf(xb1v.x, wqa1.x, a); a = fmaf(xb1v.y, wqa1.y, a); a = fmaf(xb1v.z, wqa1.z, a); a = fmaf(xb1v.w, wqa1.w, a);
            pB0 = a;
            a = xb0v.x * wqb0.x; a = fmaf(xb0v.y, wqb0.y, a); a = fmaf(xb0v.z, wqb0.z, a); a = fmaf(xb0v.w, wqb0.w, a);
            a = fmaf(xb1v.x, wqb1.x, a); a = fmaf(xb1v.y, wqb1.y, a); a = fmaf(xb1v.z, wqb1.z, a); a = fmaf(xb1v.w, wqb1.w, a);
            pB1 = a;
        }

        // specialized butterfly within the 16-lane half: outputs (2 heads x 2 segs)
        // step xor8 (2 shfls): keep head (2*half + b3), both segments
        float s1 = b3 ? pA0 : pA1;
        float r1 = __shfl_xor_sync(0xffffffffu, s1, 8);
        float uA = (b3 ? pA1 : pA0) + r1;
        float s2 = b3 ? pB0 : pB1;
        float r2 = __shfl_xor_sync(0xffffffffu, s2, 8);
        float uB = (b3 ? pB1 : pB0) + r2;
        // step xor4 (1 shfl): keep segment (b2 ? B : A)
        float s3 = b2 ? uA : uB;
        float r3 = __shfl_xor_sync(0xffffffffu, s3, 4);
        float v  = (b2 ? uB : uA) + r3;
        // steps xor2, xor1
        v += __shfl_xor_sync(0xffffffffu, v, 2);
        v += __shfl_xor_sync(0xffffffffu, v, 1);

        // leaky_relu -> exp, ONE per lane (|score| <~ 15 << 88, fp32-safe)
        float e = __expf(fmaxf(v, 0.2f * v));

        // allgather within the half (3 shfls): lane needs its 2 heads x 2 segs
        float g1 = __shfl_xor_sync(0xffffffffu, e, 4);
        float eX = b2 ? g1 : e;     // (head 2*half+b3, seg A)
        float eY = b2 ? e  : g1;    // (head 2*half+b3, seg B)
        float g2 = __shfl_xor_sync(0xffffffffu, eX, 8);
        float g3 = __shfl_xor_sync(0xffffffffu, eY, 8);
        float eA0 = b3 ? g2 : eX;   // (head 2*half,   seg A)
        float eA1 = b3 ? eX : g2;   // (head 2*half+1, seg A)
        float eB0 = b3 ? g3 : eY;   // (head 2*half,   seg B)
        float eB1 = b3 ? eY : g3;   // (head 2*half+1, seg B)

        // accumulate: 2 heads x 8 i x 2 segments
        ds0 += eA0 + eB0;
        ds1 += eA1 + eB1;
        xh0a.x = fmaf(eA0, xa0.x, xh0a.x); xh0a.y = fmaf(eA0, xa0.y, xh0a.y);
        xh0a.z = fmaf(eA0, xa0.z, xh0a.z); xh0a.w = fmaf(eA0, xa0.w, xh0a.w);
        xh0b.x = fmaf(eA0, xa1.x, xh0b.x); xh0b.y = fmaf(eA0, xa1.y, xh0b.y);
        xh0b.z = fmaf(eA0, xa1.z, xh0b.z); xh0b.w = fmaf(eA0, xa1.w, xh0b.w);
        xh1a.x = fmaf(eA1, xa0.x, xh1a.x); xh1a.y = fmaf(eA1, xa0.y, xh1a.y);
        xh1a.z = fmaf(eA1, xa0.z, xh1a.z); xh1a.w = fmaf(eA1, xa0.w, xh1a.w);
        xh1b.x = fmaf(eA1, xa1.x, xh1b.x); xh1b.y = fmaf(eA1, xa1.y, xh1b.y);
        xh1b.z = fmaf(eA1, xa1.z, xh1b.z); xh1b.w = fmaf(eA1, xa1.w, xh1b.w);

        xh0a.x = fmaf(eB0, xb0v.x, xh0a.x); xh0a.y = fmaf(eB0, xb0v.y, xh0a.y);
        xh0a.z = fmaf(eB0, xb0v.z, xh0a.z); xh0a.w = fmaf(eB0, xb0v.w, xh0a.w);
        xh0b.x = fmaf(eB0, xb1v.x, xh0b.x); xh0b.y = fmaf(eB0, xb1v.y, xh0b.y);
        xh0b.z = fmaf(eB0, xb1v.z, xh0b.z); xh0b.w = fmaf(eB0, xb1v.w, xh0b.w);
        xh1a.x = fmaf(eB1, xb0v.x, xh1a.x); xh1a.y = fmaf(eB1, xb0v.y, xh1a.y);
        xh1a.z = fmaf(eB1, xb0v.z, xh1a.z); xh1a.w = fmaf(eB1, xb0v.w, xh1a.w);
        xh1b.x = fmaf(eB1, xb1v.x, xh1b.x); xh1b.y = fmaf(eB1, xb1v.y, xh1b.y);
        xh1b.z = fmaf(eB1, xb1v.z, xh1b.z); xh1b.w = fmaf(eB1, xb1v.w, xh1b.w);
    }

    // ---- stage UNNORMALIZED xb for ALL rows into block-shared space ----
    // Row r's region at sx[r*512 + h*128 + i]; aliases other warps' ring slots,
    // so full block barrier before writing. No cross-half combine needed:
    // halves own disjoint heads, lanes own disjoint i.
    float* sx = (float*)&ring[0][0][0];
    __syncthreads();
    {
        float4* d0 = (float4*)(sx + warp * 512 + (2 * half) * IDIM + p16 * 8);
        d0[0] = xh0a;
        d0[1] = xh0b;
        float4* d1 = (float4*)(sx + warp * 512 + (2 * half + 1) * IDIM + p16 * 8);
        d1[0] = xh1a;
        d1[1] = xh1b;
    }
    if (p16 == 0) {
        sdsum[warp][2 * half]     = ds0;
        sdsum[warp][2 * half + 1] = ds1;
    }
    __syncthreads();

    // ---- cooperative epilogue: warp w = head w, lane owns 2 output cols,
    //      each W float2 load amortized across all 4 rows (8 FMAs/load) ----
    {
        const int hh = warp;              // head handled by this warp
        const int c0 = lane * 2;          // output columns c0, c0+1
        const float* Wp = W + ((size_t)hh * IDIM) * PD + c0;  // W[hh][i][c0], stride PD per i
        const float* sxh = sx + hh * IDIM;                    // + r*512 per row

        float2 acc[NWARP];
#pragma unroll
        for (int r = 0; r < NWARP; r++) acc[r] = make_float2(0.f, 0.f);

#pragma unroll 4
        for (int i = 0; i < IDIM; i++) {
            float2 wv = *(const float2*)(Wp + i * PD);         // shared by all 4 rows
#pragma unroll
            for (int r = 0; r < NWARP; r++) {
                float xv = sxh[r * 512 + i];                   // LDS broadcast
                acc[r].x = fmaf(xv, wv.x, acc[r].x);
                acc[r].y = fmaf(xv, wv.y, acc[r].y);
            }
        }

#pragma unroll
        for (int r = 0; r < NWARP; r++) {
            float inv = 1.0f / sdsum[r][hh];
            int row_r = blockIdx.x * NWARP + r;
            float2* op = (float2*)(out + (size_t)row_r * OUTD + hh * PD + c0);
            *op = make_float2(acc[r].x * inv, acc[r].y * inv);
        }
    }
}

extern "C" void kernel_launch(void* const* d_in, const int* in_sizes, int n_in,
                              void* d_out, int out_size) {
    // inputs: x [N, 12800], W [4,128,64], q [4,64] — identify defensively by size
    const float* x = (const float*)d_in[0];
    const float* W = (const float*)d_in[1];
    const float* q = (const float*)d_in[2];
    for (int i = 0; i < n_in && i < 3; i++) {
        if (in_sizes[i] == N_ROWS * SPLIT * IDIM) x = (const float*)d_in[i];
        else if (in_sizes[i] == NH * IDIM * PD)   W = (const float*)d_in[i];
        else if (in_sizes[i] == NH * PD)          q = (const float*)d_in[i];
    }
    float* out = (float*)d_out;

    wq_kernel<<<1, 512>>>(W, q);
    attn_kernel<<<N_ROWS / NWARP, NWARP * 32>>>(x, W, out);
}